// round 11
// baseline (speedup 1.0000x reference)
#include <cuda_runtime.h>

#define NB 16
#define NC 3
#define IH 720
#define IW 1280
#define OUT 255
#define PER_B (NC*IH*IW)          /* 2764800 floats per batch image */
#define PER_B4 (PER_B/4)          /* 691200 float4 per batch image */
#define RBLK 74                   /* reduce slices per batch */
#define NBLK (RBLK*NB)            /* 1184 blocks = exactly 8 per SM */
#define RSTRIDE (RBLK*128)        /* 9472 float4: stride of one 128-thread sweep */
#define NITER 73                  /* ceil(PER_B4 / RSTRIDE) */
#define NA 37                     /* half A: iters [0,37); half B: [37,73) */
#define NTILE (NB*OUT)            /* 4080 output rows */
#define NHALF (2*NBLK)            /* 2368 half-partials */

__device__ float d_partial[NHALF];
__device__ float d_mean[NB];
__device__ unsigned int d_count = 0;   /* wrapping counter -> graph-replay safe */
__device__ volatile int d_flag = 0;    /* means-ready release flag */

// ---------------------------------------------------------------------------
// Bilinear helpers (identical fp expressions in main and patch passes).
// ---------------------------------------------------------------------------
__device__ __forceinline__ void pixel_coords(int b, int oy, int ox,
                                             const float* __restrict__ pos,
                                             const float* __restrict__ szs,
                                             int& o00, int& o01, int& o10, int& o11,
                                             bool& v00, bool& v01, bool& v10, bool& v11,
                                             float& wx, float& wy) {
    const float sz    = __ldg(&szs[b]);
    const float half  = (sz + 1.0f) * 0.5f;
    const float xmin  = rintf(__ldg(&pos[2 * b + 0]) - half);   /* jnp.round */
    const float ymin  = rintf(__ldg(&pos[2 * b + 1]) - half);
    const float scale = sz / (float)OUT;
    const float szm1  = sz - 1.0f;

    float sx = fminf(fmaxf(((float)ox + 0.5f) * scale - 0.5f, 0.0f), szm1);
    float lx = floorf(sx);
    wx = sx - lx;
    float hx = fminf(lx + 1.0f, szm1);

    float sy = fminf(fmaxf(((float)oy + 0.5f) * scale - 0.5f, 0.0f), szm1);
    float ly = floorf(sy);
    wy = sy - ly;
    float hy = fminf(ly + 1.0f, szm1);

    float y0 = ly + ymin, y1 = hy + ymin;
    float x0 = lx + xmin, x1 = hx + xmin;

    bool vy0 = (y0 >= 0.0f) & (y0 <= (float)(IH - 1));
    bool vy1 = (y1 >= 0.0f) & (y1 <= (float)(IH - 1));
    bool vx0 = (x0 >= 0.0f) & (x0 <= (float)(IW - 1));
    bool vx1 = (x1 >= 0.0f) & (x1 <= (float)(IW - 1));
    int iy0 = (int)fminf(fmaxf(y0, 0.0f), (float)(IH - 1));
    int iy1 = (int)fminf(fmaxf(y1, 0.0f), (float)(IH - 1));
    int ix0 = (int)fminf(fmaxf(x0, 0.0f), (float)(IW - 1));
    int ix1 = (int)fminf(fmaxf(x1, 0.0f), (float)(IW - 1));
    v00 = vy0 & vx0; v01 = vy0 & vx1; v10 = vy1 & vx0; v11 = vy1 & vx1;
    o00 = iy0 * IW + ix0; o01 = iy0 * IW + ix1;
    o10 = iy1 * IW + ix0; o11 = iy1 * IW + ix1;
}

__device__ __forceinline__ bool pixel_main(const float* __restrict__ im,
                                           float* __restrict__ out,
                                           int b, int oy, int ox,
                                           const float* __restrict__ pos,
                                           const float* __restrict__ szs) {
    int o00, o01, o10, o11; bool v00, v01, v10, v11; float wx, wy;
    pixel_coords(b, oy, ox, pos, szs, o00, o01, o10, o11, v00, v01, v10, v11, wx, wy);

    const float omwx = 1.0f - wx, omwy = 1.0f - wy;
    const float* base = im + (size_t)b * PER_B;
    float* orow = out + ((size_t)(b * NC) * OUT + oy) * OUT + ox;

    #pragma unroll
    for (int c = 0; c < NC; c++) {
        const float* pl = base + c * (IH * IW);
        float p00 = v00 ? __ldg(&pl[o00]) : 0.0f;
        float p01 = v01 ? __ldg(&pl[o01]) : 0.0f;
        float p10 = v10 ? __ldg(&pl[o10]) : 0.0f;
        float p11 = v11 ? __ldg(&pl[o11]) : 0.0f;
        orow[c * (OUT * OUT)] =
            (p00 * omwx + p01 * wx) * omwy + (p10 * omwx + p11 * wx) * wy;
    }
    return !(v00 & v01 & v10 & v11);
}

__device__ __forceinline__ void pixel_patch(float* __restrict__ out,
                                            int b, int oy, int ox,
                                            const float* __restrict__ pos,
                                            const float* __restrict__ szs,
                                            float mean) {
    int o00, o01, o10, o11; bool v00, v01, v10, v11; float wx, wy;
    pixel_coords(b, oy, ox, pos, szs, o00, o01, o10, o11, v00, v01, v10, v11, wx, wy);

    const float omwx = 1.0f - wx, omwy = 1.0f - wy;
    const float w00 = omwx * omwy, w01 = wx * omwy;
    const float w10 = omwx * wy,  w11 = wx * wy;
    float w_inv = (v00 ? 0.0f : w00) + (v01 ? 0.0f : w01) +
                  (v10 ? 0.0f : w10) + (v11 ? 0.0f : w11);
    float add = w_inv * mean;
    float* orow = out + ((size_t)(b * NC) * OUT + oy) * OUT + ox;
    #pragma unroll
    for (int c = 0; c < NC; c++) orow[c * (OUT * OUT)] += add;
}

// ---------------------------------------------------------------------------
// Half-group submit: combine 4 warp sums (smw[base..base+3]), store the half
// partial, bump the wrapping counter; last half finalizes all means + flag.
// Called by warp 0 of the half (lane l).
// ---------------------------------------------------------------------------
__device__ __forceinline__ void submit_and_finalize(const float* smw, int base,
                                                    int slot, int l) {
    int last = 0;
    if (l == 0) {
        float hs = (smw[base] + smw[base + 1]) + (smw[base + 2] + smw[base + 3]);
        d_partial[slot] = hs;
        __threadfence();
        unsigned int old = atomicInc(&d_count, NHALF - 1);
        last = (old == NHALF - 1);
    }
    last = __shfl_sync(0xffffffffu, last, 0);
    if (last) {
        #pragma unroll 1
        for (int bb = 0; bb < NB; bb++) {
            const float* pp = &d_partial[bb * 2 * RBLK];     /* 148 per batch */
            float s2 = (__ldcg(&pp[l]) + __ldcg(&pp[l + 32])) +
                       (__ldcg(&pp[l + 64]) + __ldcg(&pp[l + 96]));
            if (l < 2 * RBLK - 128) s2 += __ldcg(&pp[l + 128]);
            #pragma unroll
            for (int o = 16; o > 0; o >>= 1)
                s2 += __shfl_down_sync(0xffffffffu, s2, o);
            if (l == 0) d_mean[bb] = s2 * (1.0f / (float)PER_B);
        }
        if (l == 0) {
            __threadfence();
            atomicExch((int*)&d_flag, 1);
        }
    }
}

// ---------------------------------------------------------------------------
// Fused kernel, symmetric two-phase schedule:
//  Half A (tid<128):  reduce [0,NA)  -> submit -> pixels {bid, bid+NBLK} -> patch
//  Half B (tid>=128): pixels {bid+2*NBLK, bid+3*NBLK} -> reduce [NA,73) -> submit -> patch
// ---------------------------------------------------------------------------
__global__ void __launch_bounds__(256, 8)
fused_kernel(const float* __restrict__ im,
             const float* __restrict__ pos,
             const float* __restrict__ szs,
             float* __restrict__ out) {
    const int tid = threadIdx.x;
    const int b   = blockIdx.y;
    const int blk = blockIdx.x;
    const int bid = b * RBLK + blk;

    __shared__ float smw[8];

    const float4* __restrict__ p = (const float4*)(im + (size_t)b * PER_B);

    if (tid < 128) {
        /* ============== HALF A ============== */
        const int i0 = blk * 128 + tid;
        float a0 = 0.f, a1 = 0.f, a2 = 0.f, a3 = 0.f;
        int j = 0;
        for (; j + 4 <= NA; j += 4) {                   /* iters 0..35 (9 quads) */
            int i = i0 + j * RSTRIDE;
            float4 v0 = p[i];
            float4 v1 = p[i + RSTRIDE];
            float4 v2 = p[i + 2 * RSTRIDE];
            float4 v3 = p[i + 3 * RSTRIDE];
            a0 += (v0.x + v0.y) + (v0.z + v0.w);
            a1 += (v1.x + v1.y) + (v1.z + v1.w);
            a2 += (v2.x + v2.y) + (v2.z + v2.w);
            a3 += (v3.x + v3.y) + (v3.z + v3.w);
        }
        for (; j < NA; j++) {                           /* iter 36; always in bounds */
            float4 v = p[i0 + j * RSTRIDE];
            a0 += (v.x + v.y) + (v.z + v.w);
        }
        float s = (a0 + a1) + (a2 + a3);
        #pragma unroll
        for (int o = 16; o > 0; o >>= 1) s += __shfl_down_sync(0xffffffffu, s, o);
        const int w = tid >> 5, l = tid & 31;
        if (l == 0) smw[w] = s;
        asm volatile("bar.sync 1, 128;" ::: "memory");
        if (w == 0) submit_and_finalize(smw, 0, bid * 2, l);

        /* pixels: tiles bid and bid+NBLK (both always < NTILE) */
        unsigned pm = 0;
        {
            int t = bid;
            int b2 = t / OUT, oy = t - b2 * OUT;
            if (pixel_main(im, out, b2, oy, tid, pos, szs))        pm |= 1u;
            if (tid + 128 < OUT &&
                pixel_main(im, out, b2, oy, tid + 128, pos, szs))  pm |= 2u;
        }
        {
            int t = bid + NBLK;
            int b2 = t / OUT, oy = t - b2 * OUT;
            if (pixel_main(im, out, b2, oy, tid, pos, szs))        pm |= 4u;
            if (tid + 128 < OUT &&
                pixel_main(im, out, b2, oy, tid + 128, pos, szs))  pm |= 8u;
        }

        if (pm) {
            while (d_flag == 0) __nanosleep(200);
            if (pm & 3u) {
                int t = bid;
                int b2 = t / OUT, oy = t - b2 * OUT;
                float mean = __ldcg(&d_mean[b2]);
                if (pm & 1u) pixel_patch(out, b2, oy, tid, pos, szs, mean);
                if (pm & 2u) pixel_patch(out, b2, oy, tid + 128, pos, szs, mean);
            }
            if (pm & 12u) {
                int t = bid + NBLK;
                int b2 = t / OUT, oy = t - b2 * OUT;
                float mean = __ldcg(&d_mean[b2]);
                if (pm & 4u) pixel_patch(out, b2, oy, tid, pos, szs, mean);
                if (pm & 8u) pixel_patch(out, b2, oy, tid + 128, pos, szs, mean);
            }
        }
    } else {
        /* ============== HALF B ============== */
        const int tid2 = tid - 128;

        /* pixels first: tiles bid+2*NBLK (always valid), bid+3*NBLK (if < NTILE) */
        unsigned pm = 0;
        {
            int t = bid + 2 * NBLK;
            int b2 = t / OUT, oy = t - b2 * OUT;
            if (pixel_main(im, out, b2, oy, tid2, pos, szs))        pm |= 1u;
            if (tid2 + 128 < OUT &&
                pixel_main(im, out, b2, oy, tid2 + 128, pos, szs))  pm |= 2u;
        }
        if (bid + 3 * NBLK < NTILE) {
            int t = bid + 3 * NBLK;
            int b2 = t / OUT, oy = t - b2 * OUT;
            if (pixel_main(im, out, b2, oy, tid2, pos, szs))        pm |= 4u;
            if (tid2 + 128 < OUT &&
                pixel_main(im, out, b2, oy, tid2 + 128, pos, szs))  pm |= 8u;
        }

        /* reduce tail: iters [NA, NITER) */
        const int i0 = blk * 128 + tid2;
        float a0 = 0.f, a1 = 0.f, a2 = 0.f, a3 = 0.f;
        int j = NA;
        for (; j + 4 <= NITER - 1; j += 4) {            /* iters 37..68 (8 quads) */
            int i = i0 + j * RSTRIDE;
            float4 v0 = p[i];
            float4 v1 = p[i + RSTRIDE];
            float4 v2 = p[i + 2 * RSTRIDE];
            float4 v3 = p[i + 3 * RSTRIDE];
            a0 += (v0.x + v0.y) + (v0.z + v0.w);
            a1 += (v1.x + v1.y) + (v1.z + v1.w);
            a2 += (v2.x + v2.y) + (v2.z + v2.w);
            a3 += (v3.x + v3.y) + (v3.z + v3.w);
        }
        for (; j < NITER; j++) {                        /* iters 69..72; 72 partial */
            int i = i0 + j * RSTRIDE;
            if (i < PER_B4) {
                float4 v = p[i];
                a0 += (v.x + v.y) + (v.z + v.w);
            }
        }
        float s = (a0 + a1) + (a2 + a3);
        #pragma unroll
        for (int o = 16; o > 0; o >>= 1) s += __shfl_down_sync(0xffffffffu, s, o);
        const int w = tid2 >> 5, l = tid2 & 31;
        if (l == 0) smw[4 + w] = s;
        asm volatile("bar.sync 2, 128;" ::: "memory");
        if (w == 0) submit_and_finalize(smw, 4, bid * 2 + 1, l);

        if (pm) {
            while (d_flag == 0) __nanosleep(200);
            if (pm & 3u) {
                int t = bid + 2 * NBLK;
                int b2 = t / OUT, oy = t - b2 * OUT;
                float mean = __ldcg(&d_mean[b2]);
                if (pm & 1u) pixel_patch(out, b2, oy, tid2, pos, szs, mean);
                if (pm & 2u) pixel_patch(out, b2, oy, tid2 + 128, pos, szs, mean);
            }
            if (pm & 12u) {
                int t = bid + 3 * NBLK;
                int b2 = t / OUT, oy = t - b2 * OUT;
                float mean = __ldcg(&d_mean[b2]);
                if (pm & 4u) pixel_patch(out, b2, oy, tid2, pos, szs, mean);
                if (pm & 8u) pixel_patch(out, b2, oy, tid2 + 128, pos, szs, mean);
            }
        }
    }
}

// ---------------------------------------------------------------------------
extern "C" void kernel_launch(void* const* d_in, const int* in_sizes, int n_in,
                              void* d_out, int out_size) {
    const float* im  = (const float*)d_in[0];
    const float* pos = (const float*)d_in[1];
    const float* szs = (const float*)d_in[2];
    float* out = (float*)d_out;

    fused_kernel<<<dim3(RBLK, NB), 256>>>(im, pos, szs, out);
}

// round 12
// speedup vs baseline: 1.0880x; 1.0880x over previous
#include <cuda_runtime.h>

#define NB 16
#define NC 3
#define IH 720
#define IW 1280
#define OUT 255
#define PER_B (NC*IH*IW)          /* 2764800 floats per batch image */
#define PER_B4 (PER_B/4)          /* 691200 float4 per batch image */
#define RPB 46                    /* reduce blocks per batch */
#define NRED (RPB*NB)             /* 736 reduce blocks (~5 per SM) */
#define NBIL 448                  /* bilinear blocks (~3 per SM) */
#define NBLK (NRED+NBIL)          /* 1184 = 8 per SM exactly */
#define RSTRIDE (RPB*256)         /* 11776 float4 per sweep */
#define NTILE (NB*OUT)            /* 4080 output rows */

__device__ float d_partial[NRED];
__device__ float d_mean[NB];
__device__ unsigned int d_count = 0;   /* wrapping counter -> graph-replay safe */
__device__ volatile int d_flag = 0;    /* means-ready release flag */

// ---------------------------------------------------------------------------
// Bilinear helpers (identical fp expressions in main and patch passes).
// ---------------------------------------------------------------------------
__device__ __forceinline__ void pixel_coords(int b, int oy, int ox,
                                             const float* __restrict__ pos,
                                             const float* __restrict__ szs,
                                             int& o00, int& o01, int& o10, int& o11,
                                             bool& v00, bool& v01, bool& v10, bool& v11,
                                             float& wx, float& wy) {
    const float sz    = __ldg(&szs[b]);
    const float half  = (sz + 1.0f) * 0.5f;
    const float xmin  = rintf(__ldg(&pos[2 * b + 0]) - half);   /* jnp.round */
    const float ymin  = rintf(__ldg(&pos[2 * b + 1]) - half);
    const float scale = sz / (float)OUT;
    const float szm1  = sz - 1.0f;

    float sx = fminf(fmaxf(((float)ox + 0.5f) * scale - 0.5f, 0.0f), szm1);
    float lx = floorf(sx);
    wx = sx - lx;
    float hx = fminf(lx + 1.0f, szm1);

    float sy = fminf(fmaxf(((float)oy + 0.5f) * scale - 0.5f, 0.0f), szm1);
    float ly = floorf(sy);
    wy = sy - ly;
    float hy = fminf(ly + 1.0f, szm1);

    float y0 = ly + ymin, y1 = hy + ymin;
    float x0 = lx + xmin, x1 = hx + xmin;

    bool vy0 = (y0 >= 0.0f) & (y0 <= (float)(IH - 1));
    bool vy1 = (y1 >= 0.0f) & (y1 <= (float)(IH - 1));
    bool vx0 = (x0 >= 0.0f) & (x0 <= (float)(IW - 1));
    bool vx1 = (x1 >= 0.0f) & (x1 <= (float)(IW - 1));
    int iy0 = (int)fminf(fmaxf(y0, 0.0f), (float)(IH - 1));
    int iy1 = (int)fminf(fmaxf(y1, 0.0f), (float)(IH - 1));
    int ix0 = (int)fminf(fmaxf(x0, 0.0f), (float)(IW - 1));
    int ix1 = (int)fminf(fmaxf(x1, 0.0f), (float)(IW - 1));
    v00 = vy0 & vx0; v01 = vy0 & vx1; v10 = vy1 & vx0; v11 = vy1 & vx1;
    o00 = iy0 * IW + ix0; o01 = iy0 * IW + ix1;
    o10 = iy1 * IW + ix0; o11 = iy1 * IW + ix1;
}

__device__ __forceinline__ bool pixel_main(const float* __restrict__ im,
                                           float* __restrict__ out,
                                           int b, int oy, int ox,
                                           const float* __restrict__ pos,
                                           const float* __restrict__ szs) {
    int o00, o01, o10, o11; bool v00, v01, v10, v11; float wx, wy;
    pixel_coords(b, oy, ox, pos, szs, o00, o01, o10, o11, v00, v01, v10, v11, wx, wy);

    const float omwx = 1.0f - wx, omwy = 1.0f - wy;
    const float* base = im + (size_t)b * PER_B;
    float* orow = out + ((size_t)(b * NC) * OUT + oy) * OUT + ox;

    #pragma unroll
    for (int c = 0; c < NC; c++) {
        const float* pl = base + c * (IH * IW);
        float p00 = v00 ? __ldg(&pl[o00]) : 0.0f;
        float p01 = v01 ? __ldg(&pl[o01]) : 0.0f;
        float p10 = v10 ? __ldg(&pl[o10]) : 0.0f;
        float p11 = v11 ? __ldg(&pl[o11]) : 0.0f;
        orow[c * (OUT * OUT)] =
            (p00 * omwx + p01 * wx) * omwy + (p10 * omwx + p11 * wx) * wy;
    }
    return !(v00 & v01 & v10 & v11);
}

__device__ __forceinline__ void pixel_patch(float* __restrict__ out,
                                            int b, int oy, int ox,
                                            const float* __restrict__ pos,
                                            const float* __restrict__ szs,
                                            float mean) {
    int o00, o01, o10, o11; bool v00, v01, v10, v11; float wx, wy;
    pixel_coords(b, oy, ox, pos, szs, o00, o01, o10, o11, v00, v01, v10, v11, wx, wy);

    const float omwx = 1.0f - wx, omwy = 1.0f - wy;
    const float w00 = omwx * omwy, w01 = wx * omwy;
    const float w10 = omwx * wy,  w11 = wx * wy;
    float w_inv = (v00 ? 0.0f : w00) + (v01 ? 0.0f : w01) +
                  (v10 ? 0.0f : w10) + (v11 ? 0.0f : w11);
    float add = w_inv * mean;
    float* orow = out + ((size_t)(b * NC) * OUT + oy) * OUT + ox;
    #pragma unroll
    for (int c = 0; c < NC; c++) orow[c * (OUT * OUT)] += add;
}

// ---------------------------------------------------------------------------
// Persistent fused kernel, SPATIAL role split:
//   bid <  NRED : reduce block (full 256-thread streaming sweep)
//   bid >= NRED : bilinear block (9-10 output rows, 1 px/thread/row)
// Reduce bids are lowest -> always scheduled first -> flag always produced
// regardless of achieved occupancy (deadlock-impossible).
// ---------------------------------------------------------------------------
__global__ void __launch_bounds__(256, 8)
fused_kernel(const float* __restrict__ im,
             const float* __restrict__ pos,
             const float* __restrict__ szs,
             float* __restrict__ out) {
    const int bid = blockIdx.x;
    const int tid = threadIdx.x;

    if (bid < NRED) {
        /* ==================== REDUCE ROLE ==================== */
        const int b   = bid / RPB;
        const int blk = bid - b * RPB;
        const float4* __restrict__ p = (const float4*)(im + (size_t)b * PER_B);
        const int i0 = blk * 256 + tid;

        /* 691200 / 11776 = 58.69 -> quads j=0..55, singles 56,57, partial 58 */
        float a0 = 0.f, a1 = 0.f, a2 = 0.f, a3 = 0.f;
        #pragma unroll 2
        for (int j = 0; j < 56; j += 4) {
            int i = i0 + j * RSTRIDE;
            float4 v0 = p[i];
            float4 v1 = p[i + RSTRIDE];
            float4 v2 = p[i + 2 * RSTRIDE];
            float4 v3 = p[i + 3 * RSTRIDE];
            a0 += (v0.x + v0.y) + (v0.z + v0.w);
            a1 += (v1.x + v1.y) + (v1.z + v1.w);
            a2 += (v2.x + v2.y) + (v2.z + v2.w);
            a3 += (v3.x + v3.y) + (v3.z + v3.w);
        }
        {
            float4 v = p[i0 + 56 * RSTRIDE];
            a0 += (v.x + v.y) + (v.z + v.w);
            float4 u = p[i0 + 57 * RSTRIDE];
            a1 += (u.x + u.y) + (u.z + u.w);
            int i = i0 + 58 * RSTRIDE;
            if (i < PER_B4) {
                float4 t = p[i];
                a2 += (t.x + t.y) + (t.z + t.w);
            }
        }
        float s = (a0 + a1) + (a2 + a3);

        __shared__ float smw[8];
        #pragma unroll
        for (int o = 16; o > 0; o >>= 1) s += __shfl_down_sync(0xffffffffu, s, o);
        const int w = tid >> 5, l = tid & 31;
        if (l == 0) smw[w] = s;
        __syncthreads();

        if (w == 0) {
            int last = 0;
            if (l == 0) {
                float bs = ((smw[0] + smw[1]) + (smw[2] + smw[3])) +
                           ((smw[4] + smw[5]) + (smw[6] + smw[7]));
                d_partial[bid] = bs;
                __threadfence();
                unsigned int old = atomicInc(&d_count, NRED - 1);
                last = (old == NRED - 1);
            }
            last = __shfl_sync(0xffffffffu, last, 0);

            if (last) {
                /* finalize all 16 means with this warp (46 partials each) */
                #pragma unroll 1
                for (int bb = 0; bb < NB; bb++) {
                    const float* pp = &d_partial[bb * RPB];
                    float s2 = __ldcg(&pp[l]);
                    if (l < RPB - 32) s2 += __ldcg(&pp[l + 32]);
                    #pragma unroll
                    for (int o = 16; o > 0; o >>= 1)
                        s2 += __shfl_down_sync(0xffffffffu, s2, o);
                    if (l == 0) d_mean[bb] = s2 * (1.0f / (float)PER_B);
                }
                if (l == 0) {
                    __threadfence();
                    atomicExch((int*)&d_flag, 1);
                }
            }
        }
    } else {
        /* ==================== BILINEAR ROLE ==================== */
        const int bbid = bid - NRED;                  /* 0..447 */
        const bool act = (tid < OUT);

        unsigned pmask = 0;                           /* bit k: tile k needs mean */
        if (act) {
            #pragma unroll 1
            for (int k = 0; k < 10; k++) {
                int t = bbid + k * NBIL;
                if (t >= NTILE) break;
                int b2 = t / OUT;
                int oy = t - b2 * OUT;
                if (pixel_main(im, out, b2, oy, tid, pos, szs))
                    pmask |= 1u << k;
            }
        }

        if (pmask) {
            while (d_flag == 0) __nanosleep(200);     /* reduce always progresses */
            #pragma unroll 1
            for (int k = 0; k < 10; k++) {
                if (!(pmask & (1u << k))) continue;
                int t = bbid + k * NBIL;
                int b2 = t / OUT;
                int oy = t - b2 * OUT;
                pixel_patch(out, b2, oy, tid, pos, szs, __ldcg(&d_mean[b2]));
            }
        }
    }
}

// ---------------------------------------------------------------------------
extern "C" void kernel_launch(void* const* d_in, const int* in_sizes, int n_in,
                              void* d_out, int out_size) {
    const float* im  = (const float*)d_in[0];
    const float* pos = (const float*)d_in[1];
    const float* szs = (const float*)d_in[2];
    float* out = (float*)d_out;

    fused_kernel<<<NBLK, 256>>>(im, pos, szs, out);
}